// round 1
// baseline (speedup 1.0000x reference)
#include <cuda_runtime.h>

#define INN   4096
#define OUTN  4096
#define KSEL  64

// Packed (idx, val_bits) pairs per output neuron: [OUTN][KSEL][2] ints = 2 MB scratch.
__device__ __align__(16) int g_pack[OUTN * KSEL * 2];

// ---------------------------------------------------------------------------
// Kernel A: per-output-row top-K selection via bitonic sort (descending).
// One block per row. Emits (idx, exp(pre_w)*sign) for the 64 largest pre_w.
// ---------------------------------------------------------------------------
__global__ void __launch_bounds__(512) topk_kernel(const float* __restrict__ pre_w,
                                                   const float* __restrict__ sign_matrix) {
    __shared__ float sval[INN];
    __shared__ short sidx[INN];

    const int row = blockIdx.x;
    const float* w = pre_w + (size_t)row * INN;

    for (int i = threadIdx.x; i < INN; i += 512) {
        sval[i] = w[i];
        sidx[i] = (short)i;
    }
    __syncthreads();

    // Bitonic sort, descending.
    for (int k = 2; k <= INN; k <<= 1) {
        for (int j = k >> 1; j > 0; j >>= 1) {
            for (int t = threadIdx.x; t < INN; t += 512) {
                int ixj = t ^ j;
                if (ixj > t) {
                    bool up = ((t & k) == 0);
                    float a = sval[t], b = sval[ixj];
                    // descending: in "up" segments larger value goes first
                    if (up ? (a < b) : (a > b)) {
                        sval[t] = b; sval[ixj] = a;
                        short ti = sidx[t]; sidx[t] = sidx[ixj]; sidx[ixj] = ti;
                    }
                }
            }
            __syncthreads();
        }
    }

    if (threadIdx.x < KSEL) {
        int k = threadIdx.x;
        int idx = (int)sidx[k];
        float v = expf(sval[k]) * sign_matrix[(size_t)row * INN + idx];
        g_pack[((size_t)row * KSEL + k) * 2 + 0] = idx;
        g_pack[((size_t)row * KSEL + k) * 2 + 1] = __float_as_int(v);
    }
}

// ---------------------------------------------------------------------------
// Kernel B: sparse gather-GEMM.
// Block = 8 batch rows. x tile transposed into smem: xsA[i] = rows 0..3 at
// column i (float4), xsB[i] = rows 4..7. Each thread owns one output neuron,
// gathers 64 columns (2x LDS.128 each) and accumulates 8 fp32 dot products.
// ---------------------------------------------------------------------------
__global__ void __launch_bounds__(512) spmm_kernel(const float* __restrict__ x,
                                                   float* __restrict__ out) {
    extern __shared__ float4 smem[];
    float4* xsA = smem;          // [INN]
    float4* xsB = smem + INN;    // [INN]

    const int b0 = blockIdx.x * 8;

    // Load + transpose 8 x-rows into smem.
    // v -> (r = v & 7, c4 = v >> 3): adjacent lanes cover 8 rows, limits STS conflicts.
    float* baseA = reinterpret_cast<float*>(xsA);
    float* baseB = reinterpret_cast<float*>(xsB);
    for (int v = threadIdx.x; v < 8 * (INN / 4); v += 512) {
        int r  = v & 7;
        int c4 = v >> 3;
        float4 d = reinterpret_cast<const float4*>(x + (size_t)(b0 + r) * INN)[c4];
        float* base = (r < 4) ? baseA : baseB;
        int rr = r & 3;
        int i0 = c4 * 4;
        base[(i0 + 0) * 4 + rr] = d.x;
        base[(i0 + 1) * 4 + rr] = d.y;
        base[(i0 + 2) * 4 + rr] = d.z;
        base[(i0 + 3) * 4 + rr] = d.w;
    }
    __syncthreads();

    for (int j = threadIdx.x; j < OUTN; j += 512) {
        float acc[8];
#pragma unroll
        for (int r = 0; r < 8; r++) acc[r] = 0.0f;

        const int4* pk = reinterpret_cast<const int4*>(&g_pack[(size_t)j * KSEL * 2]);
#pragma unroll 8
        for (int kk = 0; kk < KSEL / 2; kk++) {
            int4 p = pk[kk];  // (idx0, val0, idx1, val1)

            float v0 = __int_as_float(p.y);
            float4 a0 = xsA[p.x];
            float4 c0 = xsB[p.x];
            acc[0] += a0.x * v0; acc[1] += a0.y * v0;
            acc[2] += a0.z * v0; acc[3] += a0.w * v0;
            acc[4] += c0.x * v0; acc[5] += c0.y * v0;
            acc[6] += c0.z * v0; acc[7] += c0.w * v0;

            float v1 = __int_as_float(p.w);
            float4 a1 = xsA[p.z];
            float4 c1 = xsB[p.z];
            acc[0] += a1.x * v1; acc[1] += a1.y * v1;
            acc[2] += a1.z * v1; acc[3] += a1.w * v1;
            acc[4] += c1.x * v1; acc[5] += c1.y * v1;
            acc[6] += c1.z * v1; acc[7] += c1.w * v1;
        }

#pragma unroll
        for (int r = 0; r < 8; r++)
            out[(size_t)(b0 + r) * OUTN + j] = acc[r];
    }
}

// ---------------------------------------------------------------------------
extern "C" void kernel_launch(void* const* d_in, const int* in_sizes, int n_in,
                              void* d_out, int out_size) {
    const float* x      = (const float*)d_in[0];
    const float* pre_w  = (const float*)d_in[1];
    const float* sign_m = (const float*)d_in[2];
    float* out = (float*)d_out;

    int B = in_sizes[0] / INN;  // 8192

    const int smem_bytes = 2 * INN * (int)sizeof(float4);  // 131072
    cudaFuncSetAttribute(spmm_kernel, cudaFuncAttributeMaxDynamicSharedMemorySize, smem_bytes);

    topk_kernel<<<OUTN, 512>>>(pre_w, sign_m);
    spmm_kernel<<<B / 8, 512, smem_bytes>>>(x, out);
}

// round 3
// speedup vs baseline: 1.0950x; 1.0950x over previous
#include <cuda_runtime.h>
#include <cuda_fp16.h>
#include <cstdint>

#define INN   4096
#define OUTN  4096
#define BATCH 8192
#define KSEL  64

// Dense fp16 weight + fp16 activations (device-global scratch; no runtime alloc).
__device__ __align__(16) __half g_W[(size_t)OUTN * INN];   // 32 MB
__device__ __align__(16) __half g_X[(size_t)BATCH * INN];  // 64 MB

// ===========================================================================
// Helpers
// ===========================================================================
__device__ __forceinline__ uint32_t smem_u32(const void* p) {
    uint32_t a;
    asm("{ .reg .u64 t; cvta.to.shared.u64 t, %1; cvt.u32.u64 %0, t; }" : "=r"(a) : "l"(p));
    return a;
}
__device__ __forceinline__ void cp16(uint32_t dst, const void* src) {
    asm volatile("cp.async.cg.shared.global [%0], [%1], 16;" :: "r"(dst), "l"(src));
}
__device__ __forceinline__ void cp_commit() {
    asm volatile("cp.async.commit_group;" ::: "memory");
}
template <int N>
__device__ __forceinline__ void cp_wait() {
    asm volatile("cp.async.wait_group %0;" :: "n"(N) : "memory");
}
__device__ __forceinline__ void ldmat_x4(uint32_t& r0, uint32_t& r1, uint32_t& r2,
                                         uint32_t& r3, uint32_t addr) {
    asm volatile("ldmatrix.sync.aligned.m8n8.x4.shared.b16 {%0,%1,%2,%3}, [%4];"
                 : "=r"(r0), "=r"(r1), "=r"(r2), "=r"(r3) : "r"(addr));
}
__device__ __forceinline__ void mma16816(float* c, const uint32_t* a, const uint32_t* b) {
    asm volatile(
        "mma.sync.aligned.m16n8k16.row.col.f32.f16.f16.f32 "
        "{%0,%1,%2,%3}, {%4,%5,%6,%7}, {%8,%9}, {%0,%1,%2,%3};"
        : "+f"(c[0]), "+f"(c[1]), "+f"(c[2]), "+f"(c[3])
        : "r"(a[0]), "r"(a[1]), "r"(a[2]), "r"(a[3]), "r"(b[0]), "r"(b[1]));
}

// ===========================================================================
// Kernel A: top-K per output row (bitonic) -> dense fp16 weight row into g_W.
// ===========================================================================
__global__ void __launch_bounds__(512) build_w_kernel(const float* __restrict__ pre_w,
                                                      const float* __restrict__ sign_matrix) {
    __shared__ float  sval[INN];
    __shared__ short  sidx[INN];
    __shared__ __half hrow[INN];

    const int row = blockIdx.x;
    const float* w = pre_w + (size_t)row * INN;

    for (int i = threadIdx.x; i < INN; i += 512) {
        sval[i] = w[i];
        sidx[i] = (short)i;
        hrow[i] = __float2half(0.0f);
    }
    __syncthreads();

    for (int k = 2; k <= INN; k <<= 1) {
        for (int j = k >> 1; j > 0; j >>= 1) {
            for (int t = threadIdx.x; t < INN; t += 512) {
                int ixj = t ^ j;
                if (ixj > t) {
                    bool up = ((t & k) == 0);
                    float a = sval[t], b = sval[ixj];
                    if (up ? (a < b) : (a > b)) {
                        sval[t] = b; sval[ixj] = a;
                        short ti = sidx[t]; sidx[t] = sidx[ixj]; sidx[ixj] = ti;
                    }
                }
            }
            __syncthreads();
        }
    }

    if (threadIdx.x < KSEL) {
        int idx = (int)sidx[threadIdx.x];
        float v = expf(sval[threadIdx.x]) * sign_matrix[(size_t)row * INN + idx];
        hrow[idx] = __float2half(v);
    }
    __syncthreads();

    uint4* dst = reinterpret_cast<uint4*>(g_W + (size_t)row * INN);
    const uint4* src = reinterpret_cast<const uint4*>(hrow);
    for (int i = threadIdx.x; i < INN / 8; i += 512) dst[i] = src[i];
}

// ===========================================================================
// Kernel B: x fp32 -> fp16
// ===========================================================================
__global__ void __launch_bounds__(256) convert_x_kernel(const float* __restrict__ x) {
    const float4* x4 = reinterpret_cast<const float4*>(x);
    __half2* dst = reinterpret_cast<__half2*>(g_X);
    size_t n4 = (size_t)BATCH * INN / 4;
    size_t stride = (size_t)gridDim.x * blockDim.x;
    for (size_t v = (size_t)blockIdx.x * blockDim.x + threadIdx.x; v < n4; v += stride) {
        float4 d = x4[v];
        dst[v * 2 + 0] = __floats2half2_rn(d.x, d.y);
        dst[v * 2 + 1] = __floats2half2_rn(d.z, d.w);
    }
}

// ===========================================================================
// Kernel C: mma.sync GEMM. out[B,OUT] = g_X @ g_W^T  (both K-major fp16)
// Block tile 128x256, BK=32, 4-stage cp.async, 8 warps (2x4), warp tile 64x64.
// Smem rows padded to 80 B (64 data + 16) => conflict-free ldmatrix.
// ===========================================================================
#define BM 128
#define BN 256
#define BK 32
#define NSTAGE 4
#define ROWB 80
#define A_STAGE (BM * ROWB)                 // 10240
#define B_STAGE (BN * ROWB)                 // 20480
#define STAGE_BYTES (A_STAGE + B_STAGE)     // 30720
#define SMEM_TOTAL (NSTAGE * STAGE_BYTES)   // 122880
#define NITER (INN / BK)                    // 128

__device__ __forceinline__ void load_stage(int s, int tid, int m0, int n0, uint32_t sbase) {
    uint32_t aS = sbase + (uint32_t)(s & (NSTAGE - 1)) * STAGE_BYTES;
    uint32_t bS = aS + A_STAGE;
    const __half* aG = g_X + (size_t)m0 * INN + s * BK;
    const __half* bG = g_W + (size_t)n0 * INN + s * BK;
#pragma unroll
    for (int i = 0; i < 2; i++) {            // A: 128 rows x 4 chunks of 16 B
        int t = tid + i * 256;
        int r = t >> 2, c = t & 3;
        cp16(aS + r * ROWB + c * 16, aG + (size_t)r * INN + c * 8);
    }
#pragma unroll
    for (int i = 0; i < 4; i++) {            // B: 256 rows x 4 chunks of 16 B
        int t = tid + i * 256;
        int r = t >> 2, c = t & 3;
        cp16(bS + r * ROWB + c * 16, bG + (size_t)r * INN + c * 8);
    }
}

__global__ void __launch_bounds__(256, 1) gemm_kernel(float* __restrict__ out) {
    extern __shared__ char smem[];
    const uint32_t sbase = smem_u32(smem);
    const int tid  = threadIdx.x;
    const int lane = tid & 31;
    const int wid  = tid >> 5;
    const int m0 = blockIdx.x * BM;
    const int n0 = blockIdx.y * BN;
    const int wm = (wid & 1) * 64;           // warp M offset in tile
    const int wn = (wid >> 1) * 64;          // warp N offset in tile

    float acc[4][8][4];
#pragma unroll
    for (int mt = 0; mt < 4; mt++)
#pragma unroll
        for (int nt = 0; nt < 8; nt++)
#pragma unroll
            for (int i = 0; i < 4; i++) acc[mt][nt][i] = 0.0f;

    // Prologue: NSTAGE-1 stages in flight.
#pragma unroll
    for (int s = 0; s < NSTAGE - 1; s++) {
        load_stage(s, tid, m0, n0, sbase);
        cp_commit();
    }

    // Per-lane ldmatrix address components (constant across iters).
    const uint32_t a_row = wm + (lane & 15);
    const uint32_t a_kof = (uint32_t)(lane >> 4) * 16;              // bytes
    const uint32_t b_row = wn + (lane & 7) + ((lane >> 4) << 3);
    const uint32_t b_kof = (uint32_t)((lane >> 3) & 1) * 16;        // bytes

#pragma unroll 1
    for (int it = 0; it < NITER; it++) {
        cp_wait<NSTAGE - 2>();
        __syncthreads();

        int nxt = it + NSTAGE - 1;
        if (nxt < NITER) load_stage(nxt, tid, m0, n0, sbase);
        cp_commit();

        uint32_t aS = sbase + (uint32_t)(it & (NSTAGE - 1)) * STAGE_BYTES;
        uint32_t bS = aS + A_STAGE;

#pragma unroll
        for (int ks = 0; ks < 2; ks++) {
            const uint32_t kb = ks * 32;     // k-step byte offset (16 halves)
            uint32_t afr[4][4], bfr[8][2];
#pragma unroll
            for (int mt = 0; mt < 4; mt++)
                ldmat_x4(afr[mt][0], afr[mt][1], afr[mt][2], afr[mt][3],
                         aS + (a_row + mt * 16) * ROWB + kb + a_kof);
#pragma unroll
            for (int p = 0; p < 4; p++) {
                uint32_t r0, r1, r2, r3;
                ldmat_x4(r0, r1, r2, r3,
                         bS + (b_row + p * 16) * ROWB + kb + b_kof);
                bfr[2 * p][0] = r0; bfr[2 * p][1] = r1;
                bfr[2 * p + 1][0] = r2; bfr[2 * p + 1][1] = r3;
            }
#pragma unroll
            for (int mt = 0; mt < 4; mt++)
#pragma unroll
                for (int nt = 0; nt < 8; nt++)
                    mma16816(acc[mt][nt], afr[mt], bfr[nt]);
        }
    }

    // Epilogue: C frag (c0,c1)@(row=lane/4, col=2*(lane%4)), (c2,c3)@row+8.
    const int er = lane >> 2;
    const int ec = (lane & 3) * 2;
#pragma unroll
    for (int mt = 0; mt < 4; mt++) {
        int m = m0 + wm + mt * 16 + er;
#pragma unroll
        for (int nt = 0; nt < 8; nt++) {
            int n = n0 + wn + nt * 8 + ec;
            float2* p0 = reinterpret_cast<float2*>(out + (size_t)m * OUTN + n);
            float2* p1 = reinterpret_cast<float2*>(out + (size_t)(m + 8) * OUTN + n);
            *p0 = make_float2(acc[mt][nt][0], acc[mt][nt][1]);
            *p1 = make_float2(acc[mt][nt][2], acc[mt][nt][3]);
        }
    }
}

// ===========================================================================
extern "C" void kernel_launch(void* const* d_in, const int* in_sizes, int n_in,
                              void* d_out, int out_size) {
    const float* x      = (const float*)d_in[0];
    const float* pre_w  = (const float*)d_in[1];
    const float* sign_m = (const float*)d_in[2];
    float* out = (float*)d_out;

    cudaFuncSetAttribute(gemm_kernel, cudaFuncAttributeMaxDynamicSharedMemorySize, SMEM_TOTAL);

    build_w_kernel<<<OUTN, 512>>>(pre_w, sign_m);
    convert_x_kernel<<<4096, 256>>>(x);
    gemm_kernel<<<dim3(BATCH / BM, OUTN / BN), 256, SMEM_TOTAL>>>(out);
}

// round 5
// speedup vs baseline: 1.9171x; 1.7509x over previous
#include <cuda_runtime.h>
#include <cuda_fp16.h>
#include <cstdint>

#define INN   4096
#define OUTN  4096
#define BATCH 8192
#define KSEL  64

// Dense fp16 weight + fp16 activations (device-global scratch; no runtime alloc).
__device__ __align__(16) __half g_W[(size_t)OUTN * INN];   // 32 MB
__device__ __align__(16) __half g_X[(size_t)BATCH * INN];  // 64 MB

// ===========================================================================
// Helpers
// ===========================================================================
__device__ __forceinline__ uint32_t smem_u32(const void* p) {
    uint32_t a;
    asm("{ .reg .u64 t; cvta.to.shared.u64 t, %1; cvt.u32.u64 %0, t; }" : "=r"(a) : "l"(p));
    return a;
}
__device__ __forceinline__ void cp16(uint32_t dst, const void* src) {
    asm volatile("cp.async.cg.shared.global [%0], [%1], 16;" :: "r"(dst), "l"(src));
}
__device__ __forceinline__ void cp_commit() {
    asm volatile("cp.async.commit_group;" ::: "memory");
}
template <int N>
__device__ __forceinline__ void cp_wait() {
    asm volatile("cp.async.wait_group %0;" :: "n"(N) : "memory");
}
__device__ __forceinline__ void ldmat_x4(uint32_t& r0, uint32_t& r1, uint32_t& r2,
                                         uint32_t& r3, uint32_t addr) {
    asm volatile("ldmatrix.sync.aligned.m8n8.x4.shared.b16 {%0,%1,%2,%3}, [%4];"
                 : "=r"(r0), "=r"(r1), "=r"(r2), "=r"(r3) : "r"(addr));
}
__device__ __forceinline__ void mma16816(float* c, const uint32_t* a, const uint32_t* b) {
    asm volatile(
        "mma.sync.aligned.m16n8k16.row.col.f32.f16.f16.f32 "
        "{%0,%1,%2,%3}, {%4,%5,%6,%7}, {%8,%9}, {%0,%1,%2,%3};"
        : "+f"(c[0]), "+f"(c[1]), "+f"(c[2]), "+f"(c[3])
        : "r"(a[0]), "r"(a[1]), "r"(a[2]), "r"(a[3]), "r"(b[0]), "r"(b[1]));
}

// Monotonic float -> uint32 key (order-preserving), and its inverse.
__device__ __forceinline__ uint32_t fkey(float f) {
    uint32_t u = __float_as_uint(f);
    return (u & 0x80000000u) ? ~u : (u | 0x80000000u);
}
__device__ __forceinline__ float fkey_inv(uint32_t k) {
    uint32_t u = (k & 0x80000000u) ? (k & 0x7FFFFFFFu) : ~k;
    return __uint_as_float(u);
}

// ===========================================================================
// Kernel A: per-row top-K via 44-bit radix select on a UNIQUE composite key:
//   ck = fkey(value) << 12 | (4095 - idx)
// Value-major, lower index wins ties -> exactly matches jax.lax.top_k
// (including duplicate values). Selected set = { ck >= prefix }, always
// exactly KSEL elements since keys are unique.
// One block (256 threads) per output row; each thread owns 16 elements.
// ===========================================================================
__global__ void __launch_bounds__(256) build_w_kernel(const float* __restrict__ pre_w,
                                                      const float* __restrict__ sign_matrix) {
    __shared__ int s_warp[8];

    const int row  = blockIdx.x;
    const int tid  = threadIdx.x;
    const int lane = tid & 31;
    const int wid  = tid >> 5;

    const float4* w4 = reinterpret_cast<const float4*>(pre_w + (size_t)row * INN);

    uint64_t ck[16];
#pragma unroll
    for (int j = 0; j < 4; j++) {
        float4 v = w4[j * 256 + tid];
        int i0 = (j * 256 + tid) * 4;   // element index of v.x
        ck[j * 4 + 0] = ((uint64_t)fkey(v.x) << 12) | (uint32_t)(4095 - (i0 + 0));
        ck[j * 4 + 1] = ((uint64_t)fkey(v.y) << 12) | (uint32_t)(4095 - (i0 + 1));
        ck[j * 4 + 2] = ((uint64_t)fkey(v.z) << 12) | (uint32_t)(4095 - (i0 + 2));
        ck[j * 4 + 3] = ((uint64_t)fkey(v.w) << 12) | (uint32_t)(4095 - (i0 + 3));
    }

    // Binary search over 44 bits: largest prefix with count(ck >= prefix) >= KSEL.
    uint64_t prefix = 0;
#pragma unroll 1
    for (int bit = 43; bit >= 0; bit--) {
        uint64_t trial = prefix | (1ull << bit);
        int c = 0;
#pragma unroll
        for (int e = 0; e < 16; e++) c += (ck[e] >= trial);
#pragma unroll
        for (int off = 16; off >= 1; off >>= 1)
            c += __shfl_xor_sync(0xFFFFFFFF, c, off);
        if (lane == 0) s_warp[wid] = c;
        __syncthreads();
        int total = s_warp[0] + s_warp[1] + s_warp[2] + s_warp[3]
                  + s_warp[4] + s_warp[5] + s_warp[6] + s_warp[7];
        if (total >= KSEL) prefix = trial;
        __syncthreads();
    }

    // Emit: each thread writes its 16 elements (4 x 8B stores, coalesced).
    const float4* s4 = reinterpret_cast<const float4*>(sign_matrix + (size_t)row * INN);
    uint64_t* dst = reinterpret_cast<uint64_t*>(g_W + (size_t)row * INN);
#pragma unroll
    for (int j = 0; j < 4; j++) {
        float4 sg = s4[j * 256 + tid];
        const float* sp = reinterpret_cast<const float*>(&sg);
        __half h[4];
#pragma unroll
        for (int e = 0; e < 4; e++) {
            uint64_t k = ck[j * 4 + e];
            float f = fkey_inv((uint32_t)(k >> 12));
            float v = (k >= prefix) ? expf(f) * sp[e] : 0.0f;
            h[e] = __float2half(v);
        }
        dst[j * 256 + tid] = *reinterpret_cast<const uint64_t*>(h);
    }
}

// ===========================================================================
// Kernel B: x fp32 -> fp16
// ===========================================================================
__global__ void __launch_bounds__(256) convert_x_kernel(const float* __restrict__ x) {
    const float4* x4 = reinterpret_cast<const float4*>(x);
    __half2* dst = reinterpret_cast<__half2*>(g_X);
    size_t n4 = (size_t)BATCH * INN / 4;
    size_t stride = (size_t)gridDim.x * blockDim.x;
    for (size_t v = (size_t)blockIdx.x * blockDim.x + threadIdx.x; v < n4; v += stride) {
        float4 d = x4[v];
        dst[v * 2 + 0] = __floats2half2_rn(d.x, d.y);
        dst[v * 2 + 1] = __floats2half2_rn(d.z, d.w);
    }
}

// ===========================================================================
// Kernel C: mma.sync GEMM. out[B,OUT] = g_X @ g_W^T  (both K-major fp16)
// Block tile 128x256, BK=32, 4-stage cp.async, 8 warps (2x4), warp tile 64x64.
// Smem rows padded to 80 B (64 data + 16) => conflict-free ldmatrix.
// ===========================================================================
#define BM 128
#define BN 256
#define BK 32
#define NSTAGE 4
#define ROWB 80
#define A_STAGE (BM * ROWB)                 // 10240
#define B_STAGE (BN * ROWB)                 // 20480
#define STAGE_BYTES (A_STAGE + B_STAGE)     // 30720
#define SMEM_TOTAL (NSTAGE * STAGE_BYTES)   // 122880
#define NITER (INN / BK)                    // 128

__device__ __forceinline__ void load_stage(int s, int tid, int m0, int n0, uint32_t sbase) {
    uint32_t aS = sbase + (uint32_t)(s & (NSTAGE - 1)) * STAGE_BYTES;
    uint32_t bS = aS + A_STAGE;
    const __half* aG = g_X + (size_t)m0 * INN + s * BK;
    const __half* bG = g_W + (size_t)n0 * INN + s * BK;
#pragma unroll
    for (int i = 0; i < 2; i++) {            // A: 128 rows x 4 chunks of 16 B
        int t = tid + i * 256;
        int r = t >> 2, c = t & 3;
        cp16(aS + r * ROWB + c * 16, aG + (size_t)r * INN + c * 8);
    }
#pragma unroll
    for (int i = 0; i < 4; i++) {            // B: 256 rows x 4 chunks of 16 B
        int t = tid + i * 256;
        int r = t >> 2, c = t & 3;
        cp16(bS + r * ROWB + c * 16, bG + (size_t)r * INN + c * 8);
    }
}

__global__ void __launch_bounds__(256, 1) gemm_kernel(float* __restrict__ out) {
    extern __shared__ char smem[];
    const uint32_t sbase = smem_u32(smem);
    const int tid  = threadIdx.x;
    const int lane = tid & 31;
    const int wid  = tid >> 5;
    const int m0 = blockIdx.x * BM;
    const int n0 = blockIdx.y * BN;
    const int wm = (wid & 1) * 64;           // warp M offset in tile
    const int wn = (wid >> 1) * 64;          // warp N offset in tile

    float acc[4][8][4];
#pragma unroll
    for (int mt = 0; mt < 4; mt++)
#pragma unroll
        for (int nt = 0; nt < 8; nt++)
#pragma unroll
            for (int i = 0; i < 4; i++) acc[mt][nt][i] = 0.0f;

    // Prologue: NSTAGE-1 stages in flight.
#pragma unroll
    for (int s = 0; s < NSTAGE - 1; s++) {
        load_stage(s, tid, m0, n0, sbase);
        cp_commit();
    }

    // Per-lane ldmatrix address components (constant across iters).
    const uint32_t a_row = wm + (lane & 15);
    const uint32_t a_kof = (uint32_t)(lane >> 4) * 16;              // bytes
    const uint32_t b_row = wn + (lane & 7) + ((lane >> 4) << 3);
    const uint32_t b_kof = (uint32_t)((lane >> 3) & 1) * 16;        // bytes

#pragma unroll 1
    for (int it = 0; it < NITER; it++) {
        cp_wait<NSTAGE - 2>();
        __syncthreads();

        int nxt = it + NSTAGE - 1;
        if (nxt < NITER) load_stage(nxt, tid, m0, n0, sbase);
        cp_commit();

        uint32_t aS = sbase + (uint32_t)(it & (NSTAGE - 1)) * STAGE_BYTES;
        uint32_t bS = aS + A_STAGE;

#pragma unroll
        for (int ks = 0; ks < 2; ks++) {
            const uint32_t kb = ks * 32;     // k-step byte offset (16 halves)
            uint32_t afr[4][4], bfr[8][2];
#pragma unroll
            for (int mt = 0; mt < 4; mt++)
                ldmat_x4(afr[mt][0], afr[mt][1], afr[mt][2], afr[mt][3],
                         aS + (a_row + mt * 16) * ROWB + kb + a_kof);
#pragma unroll
            for (int p = 0; p < 4; p++) {
                uint32_t r0, r1, r2, r3;
                ldmat_x4(r0, r1, r2, r3,
                         bS + (b_row + p * 16) * ROWB + kb + b_kof);
                bfr[2 * p][0] = r0; bfr[2 * p][1] = r1;
                bfr[2 * p + 1][0] = r2; bfr[2 * p + 1][1] = r3;
            }
#pragma unroll
            for (int mt = 0; mt < 4; mt++)
#pragma unroll
                for (int nt = 0; nt < 8; nt++)
                    mma16816(acc[mt][nt], afr[mt], bfr[nt]);
        }
    }

    // Epilogue: C frag (c0,c1)@(row=lane/4, col=2*(lane%4)), (c2,c3)@row+8.
    const int er = lane >> 2;
    const int ec = (lane & 3) * 2;
#pragma unroll
    for (int mt = 0; mt < 4; mt++) {
        int m = m0 + wm + mt * 16 + er;
#pragma unroll
        for (int nt = 0; nt < 8; nt++) {
            int n = n0 + wn + nt * 8 + ec;
            float2* p0 = reinterpret_cast<float2*>(out + (size_t)m * OUTN + n);
            float2* p1 = reinterpret_cast<float2*>(out + (size_t)(m + 8) * OUTN + n);
            *p0 = make_float2(acc[mt][nt][0], acc[mt][nt][1]);
            *p1 = make_float2(acc[mt][nt][2], acc[mt][nt][3]);
        }
    }
}

// ===========================================================================
extern "C" void kernel_launch(void* const* d_in, const int* in_sizes, int n_in,
                              void* d_out, int out_size) {
    const float* x      = (const float*)d_in[0];
    const float* pre_w  = (const float*)d_in[1];
    const float* sign_m = (const float*)d_in[2];
    float* out = (float*)d_out;

    cudaFuncSetAttribute(gemm_kernel, cudaFuncAttributeMaxDynamicSharedMemorySize, SMEM_TOTAL);

    build_w_kernel<<<OUTN, 256>>>(pre_w, sign_m);
    convert_x_kernel<<<4096, 256>>>(x);
    gemm_kernel<<<dim3(BATCH / BM, OUTN / BN), 256, SMEM_TOTAL>>>(out);
}

// round 6
// speedup vs baseline: 2.4220x; 1.2634x over previous
#include <cuda_runtime.h>
#include <cuda_fp16.h>
#include <cstdint>

#define INN   4096
#define OUTN  4096
#define BATCH 8192
#define KSEL  64

// Dense fp16 weight + fp16 activations (device-global scratch; no runtime alloc).
__device__ __align__(16) __half g_W[(size_t)OUTN * INN];   // 32 MB
__device__ __align__(16) __half g_X[(size_t)BATCH * INN];  // 64 MB

// ===========================================================================
// Helpers
// ===========================================================================
__device__ __forceinline__ uint32_t smem_u32(const void* p) {
    uint32_t a;
    asm("{ .reg .u64 t; cvta.to.shared.u64 t, %1; cvt.u32.u64 %0, t; }" : "=r"(a) : "l"(p));
    return a;
}
__device__ __forceinline__ void cp16(uint32_t dst, const void* src) {
    asm volatile("cp.async.cg.shared.global [%0], [%1], 16;" :: "r"(dst), "l"(src));
}
__device__ __forceinline__ void cp_commit() {
    asm volatile("cp.async.commit_group;" ::: "memory");
}
template <int N>
__device__ __forceinline__ void cp_wait() {
    asm volatile("cp.async.wait_group %0;" :: "n"(N) : "memory");
}
__device__ __forceinline__ void ldmat_x4(uint32_t& r0, uint32_t& r1, uint32_t& r2,
                                         uint32_t& r3, uint32_t addr) {
    asm volatile("ldmatrix.sync.aligned.m8n8.x4.shared.b16 {%0,%1,%2,%3}, [%4];"
                 : "=r"(r0), "=r"(r1), "=r"(r2), "=r"(r3) : "r"(addr));
}
__device__ __forceinline__ void mma16816(float* c, const uint32_t* a, const uint32_t* b) {
    asm volatile(
        "mma.sync.aligned.m16n8k16.row.col.f32.f16.f16.f32 "
        "{%0,%1,%2,%3}, {%4,%5,%6,%7}, {%8,%9}, {%0,%1,%2,%3};"
        : "+f"(c[0]), "+f"(c[1]), "+f"(c[2]), "+f"(c[3])
        : "r"(a[0]), "r"(a[1]), "r"(a[2]), "r"(a[3]), "r"(b[0]), "r"(b[1]));
}

// Monotonic float -> uint32 key (order-preserving), and its inverse.
__device__ __forceinline__ uint32_t fkey(float f) {
    uint32_t u = __float_as_uint(f);
    return (u & 0x80000000u) ? ~u : (u | 0x80000000u);
}
__device__ __forceinline__ float fkey_inv(uint32_t k) {
    uint32_t u = (k & 0x80000000u) ? (k & 0x7FFFFFFFu) : ~k;
    return __uint_as_float(u);
}

// ===========================================================================
// Kernel A (fused): blocks [0, OUTN) build one weight row each via 32-bit
// radix-select + explicit tie ranking (matches jax.lax.top_k exactly);
// blocks [OUTN, OUTN+CONV_BLKS) convert a chunk of x fp32 -> fp16.
//
// Element layout for select: thread owns 16 CONTIGUOUS elements
// (indices tid*16 .. tid*16+15) so (tid, elem) order == index order,
// making the rare tie-rank scan correct.
// ===========================================================================
#define CONV_BLKS 4096

__global__ void __launch_bounds__(256) prep_kernel(const float* __restrict__ pre_w,
                                                   const float* __restrict__ sign_matrix,
                                                   const float* __restrict__ x) {
    const int tid = threadIdx.x;

    if (blockIdx.x >= OUTN) {
        // ---- convert x chunk ----
        int cb = blockIdx.x - OUTN;
        const float4* x4 = reinterpret_cast<const float4*>(x);
        __half2* dst = reinterpret_cast<__half2*>(g_X);
#pragma unroll
        for (int i = 0; i < 8; i++) {
            size_t v = (size_t)cb * 2048 + i * 256 + tid;
            float4 d = x4[v];
            dst[v * 2 + 0] = __floats2half2_rn(d.x, d.y);
            dst[v * 2 + 1] = __floats2half2_rn(d.z, d.w);
        }
        return;
    }

    __shared__ int s_warp[8];
    const int row  = blockIdx.x;
    const int lane = tid & 31;
    const int wid  = tid >> 5;

    const float4* w4 = reinterpret_cast<const float4*>(pre_w + (size_t)row * INN);

    uint32_t keys[16];
#pragma unroll
    for (int j = 0; j < 4; j++) {
        float4 v = w4[tid * 4 + j];
        keys[j * 4 + 0] = fkey(v.x);
        keys[j * 4 + 1] = fkey(v.y);
        keys[j * 4 + 2] = fkey(v.z);
        keys[j * 4 + 3] = fkey(v.w);
    }

    // Binary search: largest P with count(keys >= P) >= KSEL.
    uint32_t P = 0;
#pragma unroll 1
    for (int bit = 31; bit >= 0; bit--) {
        uint32_t trial = P | (1u << bit);
        unsigned c = 0;
#pragma unroll
        for (int e = 0; e < 16; e++) c += (keys[e] >= trial);
        c = __reduce_add_sync(0xFFFFFFFFu, c);
        if (lane == 0) s_warp[wid] = (int)c;
        __syncthreads();
        int total = s_warp[0] + s_warp[1] + s_warp[2] + s_warp[3]
                  + s_warp[4] + s_warp[5] + s_warp[6] + s_warp[7];
        if (total >= KSEL) P = trial;
        __syncthreads();
    }

    // Count strictly-greater and ties.
    unsigned gt = 0, eq = 0;
#pragma unroll
    for (int e = 0; e < 16; e++) {
        gt += (keys[e] > P);
        eq += (keys[e] == P);
    }
    unsigned packed = __reduce_add_sync(0xFFFFFFFFu, (gt << 16) | eq);
    if (lane == 0) s_warp[wid] = (int)packed;
    __syncthreads();
    unsigned tot = (unsigned)(s_warp[0] + s_warp[1] + s_warp[2] + s_warp[3]
                            + s_warp[4] + s_warp[5] + s_warp[6] + s_warp[7]);
    const int total_gt = (int)(tot >> 16);
    const int total_eq = (int)(tot & 0xFFFFu);
    const int sel_ties = KSEL - total_gt;
    const bool common = (total_eq == sel_ties);

    int offset = 0;
    if (!common) {
        // Rank ties by global element index (thread-contiguous layout => tid order).
        __syncthreads();
        int v = (int)eq;
#pragma unroll
        for (int off = 1; off < 32; off <<= 1) {
            int n = __shfl_up_sync(0xFFFFFFFFu, v, off);
            if (lane >= off) v += n;
        }
        int excl = v - (int)eq;
        if (lane == 31) s_warp[wid] = v;
        __syncthreads();
        int wpre = 0;
#pragma unroll
        for (int w = 0; w < 8; w++) wpre += (w < wid) ? s_warp[w] : 0;
        offset = wpre + excl;
    }

    // Emit dense fp16 row.
    const float4* s4 = reinterpret_cast<const float4*>(sign_matrix + (size_t)row * INN);
    uint64_t* dst = reinterpret_cast<uint64_t*>(g_W + (size_t)row * INN);
    int cnt = 0;
#pragma unroll
    for (int j = 0; j < 4; j++) {
        float4 sg = s4[tid * 4 + j];
        const float* sp = reinterpret_cast<const float*>(&sg);
        __half h[4];
#pragma unroll
        for (int e = 0; e < 4; e++) {
            uint32_t k = keys[j * 4 + e];
            bool sel = false;
            if (k > P) sel = true;
            else if (k == P) {
                sel = common ? true : ((offset + cnt) < sel_ties);
                cnt++;
            }
            float f = fkey_inv(k);
            h[e] = __float2half(sel ? expf(f) * sp[e] : 0.0f);
        }
        dst[tid * 4 + j] = *reinterpret_cast<const uint64_t*>(h);
    }
}

// ===========================================================================
// Kernel C: mma.sync GEMM. out[B,OUT] = g_X @ g_W^T  (both K-major fp16)
// Block tile 128x256, BK=64, 4-stage cp.async, 8 warps (2x4), warp tile 64x64.
// Smem rows 144 B (128 data + 16 pad) => conflict-free ldmatrix.
// Fragments double-buffered across the 4 k-steps of each stage.
// ===========================================================================
#define BM 128
#define BN 256
#define BK 64
#define NSTAGE 4
#define ROWB 144
#define A_STAGE (BM * ROWB)                 // 18432
#define B_STAGE (BN * ROWB)                 // 36864
#define STAGE_BYTES (A_STAGE + B_STAGE)     // 55296
#define SMEM_TOTAL (NSTAGE * STAGE_BYTES)   // 221184
#define NITER (INN / BK)                    // 64

__device__ __forceinline__ void load_stage(int s, int tid, int m0, int n0, uint32_t sbase) {
    uint32_t aS = sbase + (uint32_t)(s & (NSTAGE - 1)) * STAGE_BYTES;
    uint32_t bS = aS + A_STAGE;
    const __half* aG = g_X + (size_t)m0 * INN + s * BK;
    const __half* bG = g_W + (size_t)n0 * INN + s * BK;
#pragma unroll
    for (int i = 0; i < 4; i++) {            // A: 128 rows x 8 chunks of 16 B
        int t = tid + i * 256;
        int r = t >> 3, c = t & 7;
        cp16(aS + r * ROWB + c * 16, aG + (size_t)r * INN + c * 8);
    }
#pragma unroll
    for (int i = 0; i < 8; i++) {            // B: 256 rows x 8 chunks of 16 B
        int t = tid + i * 256;
        int r = t >> 3, c = t & 7;
        cp16(bS + r * ROWB + c * 16, bG + (size_t)r * INN + c * 8);
    }
}

__device__ __forceinline__ void load_frags(uint32_t aS, uint32_t bS, uint32_t kb,
                                           uint32_t a_row, uint32_t a_kof,
                                           uint32_t b_row, uint32_t b_kof,
                                           uint32_t afr[4][4], uint32_t bfr[8][2]) {
#pragma unroll
    for (int mt = 0; mt < 4; mt++)
        ldmat_x4(afr[mt][0], afr[mt][1], afr[mt][2], afr[mt][3],
                 aS + (a_row + mt * 16) * ROWB + kb + a_kof);
#pragma unroll
    for (int p = 0; p < 4; p++) {
        uint32_t r0, r1, r2, r3;
        ldmat_x4(r0, r1, r2, r3, bS + (b_row + p * 16) * ROWB + kb + b_kof);
        bfr[2 * p][0] = r0;     bfr[2 * p][1] = r1;
        bfr[2 * p + 1][0] = r2; bfr[2 * p + 1][1] = r3;
    }
}

__global__ void __launch_bounds__(256, 1) gemm_kernel(float* __restrict__ out) {
    extern __shared__ char smem[];
    const uint32_t sbase = smem_u32(smem);
    const int tid  = threadIdx.x;
    const int lane = tid & 31;
    const int wid  = tid >> 5;
    const int m0 = blockIdx.x * BM;
    const int n0 = blockIdx.y * BN;
    const int wm = (wid & 1) * 64;
    const int wn = (wid >> 1) * 64;

    float acc[4][8][4];
#pragma unroll
    for (int mt = 0; mt < 4; mt++)
#pragma unroll
        for (int nt = 0; nt < 8; nt++)
#pragma unroll
            for (int i = 0; i < 4; i++) acc[mt][nt][i] = 0.0f;

#pragma unroll
    for (int s = 0; s < NSTAGE - 1; s++) {
        load_stage(s, tid, m0, n0, sbase);
        cp_commit();
    }

    const uint32_t a_row = wm + (lane & 15);
    const uint32_t a_kof = (uint32_t)(lane >> 4) * 16;
    const uint32_t b_row = wn + (lane & 7) + ((lane >> 4) << 3);
    const uint32_t b_kof = (uint32_t)((lane >> 3) & 1) * 16;

    uint32_t afr[2][4][4], bfr[2][8][2];

#pragma unroll 1
    for (int it = 0; it < NITER; it++) {
        cp_wait<NSTAGE - 2>();
        __syncthreads();

        int nxt = it + NSTAGE - 1;
        if (nxt < NITER) load_stage(nxt, tid, m0, n0, sbase);
        cp_commit();

        uint32_t aS = sbase + (uint32_t)(it & (NSTAGE - 1)) * STAGE_BYTES;
        uint32_t bS = aS + A_STAGE;

        load_frags(aS, bS, 0, a_row, a_kof, b_row, b_kof, afr[0], bfr[0]);
#pragma unroll
        for (int ks = 0; ks < 4; ks++) {
            if (ks < 3)
                load_frags(aS, bS, (uint32_t)(ks + 1) * 32, a_row, a_kof, b_row, b_kof,
                           afr[(ks + 1) & 1], bfr[(ks + 1) & 1]);
            uint32_t (*af)[4] = afr[ks & 1];
            uint32_t (*bf)[2] = bfr[ks & 1];
#pragma unroll
            for (int mt = 0; mt < 4; mt++)
#pragma unroll
                for (int nt = 0; nt < 8; nt++)
                    mma16816(acc[mt][nt], af[mt], bf[nt]);
        }
    }

    // Epilogue.
    const int er = lane >> 2;
    const int ec = (lane & 3) * 2;
#pragma unroll
    for (int mt = 0; mt < 4; mt++) {
        int m = m0 + wm + mt * 16 + er;
#pragma unroll
        for (int nt = 0; nt < 8; nt++) {
            int n = n0 + wn + nt * 8 + ec;
            float2* p0 = reinterpret_cast<float2*>(out + (size_t)m * OUTN + n);
            float2* p1 = reinterpret_cast<float2*>(out + (size_t)(m + 8) * OUTN + n);
            *p0 = make_float2(acc[mt][nt][0], acc[mt][nt][1]);
            *p1 = make_float2(acc[mt][nt][2], acc[mt][nt][3]);
        }
    }
}

// ===========================================================================
extern "C" void kernel_launch(void* const* d_in, const int* in_sizes, int n_in,
                              void* d_out, int out_size) {
    const float* x      = (const float*)d_in[0];
    const float* pre_w  = (const float*)d_in[1];
    const float* sign_m = (const float*)d_in[2];
    float* out = (float*)d_out;

    cudaFuncSetAttribute(gemm_kernel, cudaFuncAttributeMaxDynamicSharedMemorySize, SMEM_TOTAL);

    prep_kernel<<<OUTN + CONV_BLKS, 256>>>(pre_w, sign_m, x);
    gemm_kernel<<<dim3(BATCH / BM, OUTN / BN), 256, SMEM_TOTAL>>>(out);
}

// round 7
// speedup vs baseline: 2.6567x; 1.0969x over previous
#include <cuda_runtime.h>
#include <cuda_fp16.h>
#include <cstdint>

#define INN   4096
#define OUTN  4096
#define BATCH 8192
#define KSEL  64

// Dense fp16 weight + fp16 activations (device-global scratch; no runtime alloc).
__device__ __align__(16) __half g_W[(size_t)OUTN * INN];   // 32 MB
__device__ __align__(16) __half g_X[(size_t)BATCH * INN];  // 64 MB

// ===========================================================================
// Helpers
// ===========================================================================
__device__ __forceinline__ uint32_t smem_u32(const void* p) {
    uint32_t a;
    asm("{ .reg .u64 t; cvta.to.shared.u64 t, %1; cvt.u32.u64 %0, t; }" : "=r"(a) : "l"(p));
    return a;
}
__device__ __forceinline__ void cp16(uint32_t dst, const void* src) {
    asm volatile("cp.async.cg.shared.global [%0], [%1], 16;" :: "r"(dst), "l"(src));
}
__device__ __forceinline__ void cp_commit() {
    asm volatile("cp.async.commit_group;" ::: "memory");
}
template <int N>
__device__ __forceinline__ void cp_wait() {
    asm volatile("cp.async.wait_group %0;" :: "n"(N) : "memory");
}
__device__ __forceinline__ void ldmat_x4(uint32_t& r0, uint32_t& r1, uint32_t& r2,
                                         uint32_t& r3, uint32_t addr) {
    asm volatile("ldmatrix.sync.aligned.m8n8.x4.shared.b16 {%0,%1,%2,%3}, [%4];"
                 : "=r"(r0), "=r"(r1), "=r"(r2), "=r"(r3) : "r"(addr));
}
__device__ __forceinline__ void mma16816(float* c, const uint32_t* a, const uint32_t* b) {
    asm volatile(
        "mma.sync.aligned.m16n8k16.row.col.f32.f16.f16.f32 "
        "{%0,%1,%2,%3}, {%4,%5,%6,%7}, {%8,%9}, {%0,%1,%2,%3};"
        : "+f"(c[0]), "+f"(c[1]), "+f"(c[2]), "+f"(c[3])
        : "r"(a[0]), "r"(a[1]), "r"(a[2]), "r"(a[3]), "r"(b[0]), "r"(b[1]));
}

// Monotonic float -> uint32 key (order-preserving), and its inverse.
__device__ __forceinline__ uint32_t fkey(float f) {
    uint32_t u = __float_as_uint(f);
    return (u & 0x80000000u) ? ~u : (u | 0x80000000u);
}
__device__ __forceinline__ float fkey_inv(uint32_t k) {
    uint32_t u = (k & 0x80000000u) ? (k & 0x7FFFFFFFu) : ~k;
    return __uint_as_float(u);
}

// ===========================================================================
// Kernel A (fused): blocks [0, OUTN) build one weight row each via 32-bit
// radix-select + explicit tie ranking (matches jax.lax.top_k exactly);
// blocks [OUTN, OUTN+CONV_BLKS) convert a chunk of x fp32 -> fp16.
// ===========================================================================
#define CONV_BLKS 4096

__global__ void __launch_bounds__(256) prep_kernel(const float* __restrict__ pre_w,
                                                   const float* __restrict__ sign_matrix,
                                                   const float* __restrict__ x) {
    const int tid = threadIdx.x;

    if (blockIdx.x >= OUTN) {
        // ---- convert x chunk ----
        int cb = blockIdx.x - OUTN;
        const float4* x4 = reinterpret_cast<const float4*>(x);
        __half2* dst = reinterpret_cast<__half2*>(g_X);
#pragma unroll
        for (int i = 0; i < 8; i++) {
            size_t v = (size_t)cb * 2048 + i * 256 + tid;
            float4 d = x4[v];
            dst[v * 2 + 0] = __floats2half2_rn(d.x, d.y);
            dst[v * 2 + 1] = __floats2half2_rn(d.z, d.w);
        }
        return;
    }

    __shared__ int s_warp[8];
    const int row  = blockIdx.x;
    const int lane = tid & 31;
    const int wid  = tid >> 5;

    const float4* w4 = reinterpret_cast<const float4*>(pre_w + (size_t)row * INN);

    uint32_t keys[16];
#pragma unroll
    for (int j = 0; j < 4; j++) {
        float4 v = w4[tid * 4 + j];
        keys[j * 4 + 0] = fkey(v.x);
        keys[j * 4 + 1] = fkey(v.y);
        keys[j * 4 + 2] = fkey(v.z);
        keys[j * 4 + 3] = fkey(v.w);
    }

    // Binary search: largest P with count(keys >= P) >= KSEL.
    uint32_t P = 0;
#pragma unroll 1
    for (int bit = 31; bit >= 0; bit--) {
        uint32_t trial = P | (1u << bit);
        unsigned c = 0;
#pragma unroll
        for (int e = 0; e < 16; e++) c += (keys[e] >= trial);
        c = __reduce_add_sync(0xFFFFFFFFu, c);
        if (lane == 0) s_warp[wid] = (int)c;
        __syncthreads();
        int total = s_warp[0] + s_warp[1] + s_warp[2] + s_warp[3]
                  + s_warp[4] + s_warp[5] + s_warp[6] + s_warp[7];
        if (total >= KSEL) P = trial;
        __syncthreads();
    }

    // Count strictly-greater and ties.
    unsigned gt = 0, eq = 0;
#pragma unroll
    for (int e = 0; e < 16; e++) {
        gt += (keys[e] > P);
        eq += (keys[e] == P);
    }
    unsigned packed = __reduce_add_sync(0xFFFFFFFFu, (gt << 16) | eq);
    if (lane == 0) s_warp[wid] = (int)packed;
    __syncthreads();
    unsigned tot = (unsigned)(s_warp[0] + s_warp[1] + s_warp[2] + s_warp[3]
                            + s_warp[4] + s_warp[5] + s_warp[6] + s_warp[7]);
    const int total_gt = (int)(tot >> 16);
    const int total_eq = (int)(tot & 0xFFFFu);
    const int sel_ties = KSEL - total_gt;
    const bool common = (total_eq == sel_ties);

    int offset = 0;
    if (!common) {
        // Rank ties by global element index (thread-contiguous layout => tid order).
        __syncthreads();
        int v = (int)eq;
#pragma unroll
        for (int off = 1; off < 32; off <<= 1) {
            int n = __shfl_up_sync(0xFFFFFFFFu, v, off);
            if (lane >= off) v += n;
        }
        int excl = v - (int)eq;
        if (lane == 31) s_warp[wid] = v;
        __syncthreads();
        int wpre = 0;
#pragma unroll
        for (int w = 0; w < 8; w++) wpre += (w < wid) ? s_warp[w] : 0;
        offset = wpre + excl;
    }

    // Emit dense fp16 row.
    const float4* s4 = reinterpret_cast<const float4*>(sign_matrix + (size_t)row * INN);
    uint64_t* dst = reinterpret_cast<uint64_t*>(g_W + (size_t)row * INN);
    int cnt = 0;
#pragma unroll
    for (int j = 0; j < 4; j++) {
        float4 sg = s4[tid * 4 + j];
        const float* sp = reinterpret_cast<const float*>(&sg);
        __half h[4];
#pragma unroll
        for (int e = 0; e < 4; e++) {
            uint32_t k = keys[j * 4 + e];
            bool sel = false;
            if (k > P) sel = true;
            else if (k == P) {
                sel = common ? true : ((offset + cnt) < sel_ties);
                cnt++;
            }
            float f = fkey_inv(k);
            h[e] = __float2half(sel ? expf(f) * sp[e] : 0.0f);
        }
        dst[tid * 4 + j] = *reinterpret_cast<const uint64_t*>(h);
    }
}

// ===========================================================================
// Kernel C: mma.sync GEMM. out[B,OUT] = g_X @ g_W^T  (both K-major fp16)
// Block tile 128x256, BK=64, 4-stage cp.async.
// 512 threads = 16 warps in 2(M) x 8(N); warp tile 64x32.
// Smem rows 144 B (128 data + 16 pad) => conflict-free ldmatrix.
// ===========================================================================
#define BM 128
#define BN 256
#define BK 64
#define NSTAGE 4
#define ROWB 144
#define A_STAGE (BM * ROWB)                 // 18432
#define B_STAGE (BN * ROWB)                 // 36864
#define STAGE_BYTES (A_STAGE + B_STAGE)     // 55296
#define SMEM_TOTAL (NSTAGE * STAGE_BYTES)   // 221184
#define NITER (INN / BK)                    // 64
#define GTHREADS 512

__device__ __forceinline__ void load_stage(int s, int tid, int m0, int n0, uint32_t sbase) {
    uint32_t aS = sbase + (uint32_t)(s & (NSTAGE - 1)) * STAGE_BYTES;
    uint32_t bS = aS + A_STAGE;
    const __half* aG = g_X + (size_t)m0 * INN + s * BK;
    const __half* bG = g_W + (size_t)n0 * INN + s * BK;
#pragma unroll
    for (int i = 0; i < 2; i++) {            // A: 128 rows x 8 chunks of 16 B
        int t = tid + i * GTHREADS;
        int r = t >> 3, c = t & 7;
        cp16(aS + r * ROWB + c * 16, aG + (size_t)r * INN + c * 8);
    }
#pragma unroll
    for (int i = 0; i < 4; i++) {            // B: 256 rows x 8 chunks of 16 B
        int t = tid + i * GTHREADS;
        int r = t >> 3, c = t & 7;
        cp16(bS + r * ROWB + c * 16, bG + (size_t)r * INN + c * 8);
    }
}

__global__ void __launch_bounds__(GTHREADS, 1) gemm_kernel(float* __restrict__ out) {
    extern __shared__ char smem[];
    const uint32_t sbase = smem_u32(smem);
    const int tid  = threadIdx.x;
    const int lane = tid & 31;
    const int wid  = tid >> 5;
    const int m0 = blockIdx.x * BM;
    const int n0 = blockIdx.y * BN;
    const int wm = (wid & 1) * 64;           // 2 warps along M
    const int wn = (wid >> 1) * 32;          // 8 warps along N

    float acc[4][4][4];
#pragma unroll
    for (int mt = 0; mt < 4; mt++)
#pragma unroll
        for (int nt = 0; nt < 4; nt++)
#pragma unroll
            for (int i = 0; i < 4; i++) acc[mt][nt][i] = 0.0f;

#pragma unroll
    for (int s = 0; s < NSTAGE - 1; s++) {
        load_stage(s, tid, m0, n0, sbase);
        cp_commit();
    }

    const uint32_t a_row = wm + (lane & 15);
    const uint32_t a_kof = (uint32_t)(lane >> 4) * 16;
    const uint32_t b_row = wn + (lane & 7) + ((lane >> 4) << 3);
    const uint32_t b_kof = (uint32_t)((lane >> 3) & 1) * 16;

#pragma unroll 1
    for (int it = 0; it < NITER; it++) {
        cp_wait<NSTAGE - 2>();
        __syncthreads();

        int nxt = it + NSTAGE - 1;
        if (nxt < NITER) load_stage(nxt, tid, m0, n0, sbase);
        cp_commit();

        uint32_t aS = sbase + (uint32_t)(it & (NSTAGE - 1)) * STAGE_BYTES;
        uint32_t bS = aS + A_STAGE;

#pragma unroll
        for (int ks = 0; ks < 4; ks++) {
            const uint32_t kb = (uint32_t)ks * 32;   // 16 halves per k-step
            uint32_t afr[4][4], bfr[4][2];
#pragma unroll
            for (int mt = 0; mt < 4; mt++)
                ldmat_x4(afr[mt][0], afr[mt][1], afr[mt][2], afr[mt][3],
                         aS + (a_row + mt * 16) * ROWB + kb + a_kof);
#pragma unroll
            for (int p = 0; p < 2; p++) {
                uint32_t r0, r1, r2, r3;
                ldmat_x4(r0, r1, r2, r3, bS + (b_row + p * 16) * ROWB + kb + b_kof);
                bfr[2 * p][0] = r0;     bfr[2 * p][1] = r1;
                bfr[2 * p + 1][0] = r2; bfr[2 * p + 1][1] = r3;
            }
#pragma unroll
            for (int mt = 0; mt < 4; mt++)
#pragma unroll
                for (int nt = 0; nt < 4; nt++)
                    mma16816(acc[mt][nt], afr[mt], bfr[nt]);
        }
    }

    // Epilogue.
    const int er = lane >> 2;
    const int ec = (lane & 3) * 2;
#pragma unroll
    for (int mt = 0; mt < 4; mt++) {
        int m = m0 + wm + mt * 16 + er;
#pragma unroll
        for (int nt = 0; nt < 4; nt++) {
            int n = n0 + wn + nt * 8 + ec;
            float2* p0 = reinterpret_cast<float2*>(out + (size_t)m * OUTN + n);
            float2* p1 = reinterpret_cast<float2*>(out + (size_t)(m + 8) * OUTN + n);
            *p0 = make_float2(acc[mt][nt][0], acc[mt][nt][1]);
            *p1 = make_float2(acc[mt][nt][2], acc[mt][nt][3]);
        }
    }
}

// ===========================================================================
extern "C" void kernel_launch(void* const* d_in, const int* in_sizes, int n_in,
                              void* d_out, int out_size) {
    const float* x      = (const float*)d_in[0];
    const float* pre_w  = (const float*)d_in[1];
    const float* sign_m = (const float*)d_in[2];
    float* out = (float*)d_out;

    cudaFuncSetAttribute(gemm_kernel, cudaFuncAttributeMaxDynamicSharedMemorySize, SMEM_TOTAL);

    prep_kernel<<<OUTN + CONV_BLKS, 256>>>(pre_w, sign_m, x);
    gemm_kernel<<<dim3(BATCH / BM, OUTN / BN), GTHREADS, SMEM_TOTAL>>>(out);
}

// round 8
// speedup vs baseline: 2.9871x; 1.1243x over previous
#include <cuda_runtime.h>
#include <cuda_fp16.h>
#include <cstdint>

#define INN   4096
#define OUTN  4096
#define BATCH 8192
#define KSEL  64

// Dense fp16 weight + fp16 activations (device-global scratch; no runtime alloc).
__device__ __align__(16) __half g_W[(size_t)OUTN * INN];   // 32 MB
__device__ __align__(16) __half g_X[(size_t)BATCH * INN];  // 64 MB

// ===========================================================================
// Helpers
// ===========================================================================
__device__ __forceinline__ uint32_t smem_u32(const void* p) {
    uint32_t a;
    asm("{ .reg .u64 t; cvta.to.shared.u64 t, %1; cvt.u32.u64 %0, t; }" : "=r"(a) : "l"(p));
    return a;
}
__device__ __forceinline__ void cp16(uint32_t dst, const void* src) {
    asm volatile("cp.async.cg.shared.global [%0], [%1], 16;" :: "r"(dst), "l"(src));
}
__device__ __forceinline__ void ldmat_x4(uint32_t& r0, uint32_t& r1, uint32_t& r2,
                                         uint32_t& r3, uint32_t addr) {
    asm volatile("ldmatrix.sync.aligned.m8n8.x4.shared.b16 {%0,%1,%2,%3}, [%4];"
                 : "=r"(r0), "=r"(r1), "=r"(r2), "=r"(r3) : "r"(addr));
}
__device__ __forceinline__ void mma16816(float* c, const uint32_t* a, const uint32_t* b) {
    asm volatile(
        "mma.sync.aligned.m16n8k16.row.col.f32.f16.f16.f32 "
        "{%0,%1,%2,%3}, {%4,%5,%6,%7}, {%8,%9}, {%0,%1,%2,%3};"
        : "+f"(c[0]), "+f"(c[1]), "+f"(c[2]), "+f"(c[3])
        : "r"(a[0]), "r"(a[1]), "r"(a[2]), "r"(a[3]), "r"(b[0]), "r"(b[1]));
}

#define MBARRIER_INIT(addr, cnt) \
    asm volatile("mbarrier.init.shared.b64 [%0], %1;" :: "r"(addr), "r"((uint32_t)(cnt)) : "memory")
#define MBARRIER_ARRIVE(addr) \
    asm volatile("mbarrier.arrive.shared.b64 _, [%0];" :: "r"(addr) : "memory")
#define CP_MBAR_ARRIVE(addr) \
    asm volatile("cp.async.mbarrier.arrive.noinc.shared.b64 [%0];" :: "r"(addr) : "memory")
#define MBARRIER_WAIT_PARITY(addr, par) do {                                          \
    uint32_t _m = (addr); uint32_t _p = (par); uint32_t _d;                           \
    asm volatile("{ .reg .pred p; mbarrier.try_wait.parity.acquire.cta.shared::cta.b64 p, [%1], %2; selp.b32 %0,1,0,p; }" \
        : "=r"(_d) : "r"(_m), "r"(_p) : "memory");                                    \
    if (!_d) {                                                                        \
        asm volatile("{ .reg .pred P1; WL_%=: mbarrier.try_wait.parity.acquire.cta.shared::cta.b64 P1, [%0], %1, 0x989680; @P1 bra.uni WD_%=; bra.uni WL_%=; WD_%=: }" \
            :: "r"(_m), "r"(_p) : "memory");                                          \
    }                                                                                 \
} while (0)

// Monotonic float -> uint32 key (order-preserving), and its inverse.
__device__ __forceinline__ uint32_t fkey(float f) {
    uint32_t u = __float_as_uint(f);
    return (u & 0x80000000u) ? ~u : (u | 0x80000000u);
}
__device__ __forceinline__ float fkey_inv(uint32_t k) {
    uint32_t u = (k & 0x80000000u) ? (k & 0x7FFFFFFFu) : ~k;
    return __uint_as_float(u);
}

// ===========================================================================
// Kernel A (fused): blocks [0, OUTN) build one weight row each via 32-bit
// radix-select + explicit tie ranking (matches jax.lax.top_k exactly);
// blocks [OUTN, OUTN+CONV_BLKS) convert a chunk of x fp32 -> fp16.
// ===========================================================================
#define CONV_BLKS 4096

__global__ void __launch_bounds__(256) prep_kernel(const float* __restrict__ pre_w,
                                                   const float* __restrict__ sign_matrix,
                                                   const float* __restrict__ x) {
    const int tid = threadIdx.x;

    if (blockIdx.x >= OUTN) {
        // ---- convert x chunk ----
        int cb = blockIdx.x - OUTN;
        const float4* x4 = reinterpret_cast<const float4*>(x);
        __half2* dst = reinterpret_cast<__half2*>(g_X);
#pragma unroll
        for (int i = 0; i < 8; i++) {
            size_t v = (size_t)cb * 2048 + i * 256 + tid;
            float4 d = x4[v];
            dst[v * 2 + 0] = __floats2half2_rn(d.x, d.y);
            dst[v * 2 + 1] = __floats2half2_rn(d.z, d.w);
        }
        return;
    }

    __shared__ int s_warp[8];
    const int row  = blockIdx.x;
    const int lane = tid & 31;
    const int wid  = tid >> 5;

    const float4* w4 = reinterpret_cast<const float4*>(pre_w + (size_t)row * INN);

    uint32_t keys[16];
#pragma unroll
    for (int j = 0; j < 4; j++) {
        float4 v = w4[tid * 4 + j];
        keys[j * 4 + 0] = fkey(v.x);
        keys[j * 4 + 1] = fkey(v.y);
        keys[j * 4 + 2] = fkey(v.z);
        keys[j * 4 + 3] = fkey(v.w);
    }

    // Binary search: largest P with count(keys >= P) >= KSEL.
    uint32_t P = 0;
#pragma unroll 1
    for (int bit = 31; bit >= 0; bit--) {
        uint32_t trial = P | (1u << bit);
        unsigned c = 0;
#pragma unroll
        for (int e = 0; e < 16; e++) c += (keys[e] >= trial);
        c = __reduce_add_sync(0xFFFFFFFFu, c);
        if (lane == 0) s_warp[wid] = (int)c;
        __syncthreads();
        int total = s_warp[0] + s_warp[1] + s_warp[2] + s_warp[3]
                  + s_warp[4] + s_warp[5] + s_warp[6] + s_warp[7];
        if (total >= KSEL) P = trial;
        __syncthreads();
    }

    // Count strictly-greater and ties.
    unsigned gt = 0, eq = 0;
#pragma unroll
    for (int e = 0; e < 16; e++) {
        gt += (keys[e] > P);
        eq += (keys[e] == P);
    }
    unsigned packed = __reduce_add_sync(0xFFFFFFFFu, (gt << 16) | eq);
    if (lane == 0) s_warp[wid] = (int)packed;
    __syncthreads();
    unsigned tot = (unsigned)(s_warp[0] + s_warp[1] + s_warp[2] + s_warp[3]
                            + s_warp[4] + s_warp[5] + s_warp[6] + s_warp[7]);
    const int total_gt = (int)(tot >> 16);
    const int total_eq = (int)(tot & 0xFFFFu);
    const int sel_ties = KSEL - total_gt;
    const bool common = (total_eq == sel_ties);

    int offset = 0;
    if (!common) {
        // Rank ties by global element index (thread-contiguous layout => tid order).
        __syncthreads();
        int v = (int)eq;
#pragma unroll
        for (int off = 1; off < 32; off <<= 1) {
            int n = __shfl_up_sync(0xFFFFFFFFu, v, off);
            if (lane >= off) v += n;
        }
        int excl = v - (int)eq;
        if (lane == 31) s_warp[wid] = v;
        __syncthreads();
        int wpre = 0;
#pragma unroll
        for (int w = 0; w < 8; w++) wpre += (w < wid) ? s_warp[w] : 0;
        offset = wpre + excl;
    }

    // Emit dense fp16 row.
    const float4* s4 = reinterpret_cast<const float4*>(sign_matrix + (size_t)row * INN);
    uint64_t* dst = reinterpret_cast<uint64_t*>(g_W + (size_t)row * INN);
    int cnt = 0;
#pragma unroll
    for (int j = 0; j < 4; j++) {
        float4 sg = s4[tid * 4 + j];
        const float* sp = reinterpret_cast<const float*>(&sg);
        __half h[4];
#pragma unroll
        for (int e = 0; e < 4; e++) {
            uint32_t k = keys[j * 4 + e];
            bool sel = false;
            if (k > P) sel = true;
            else if (k == P) {
                sel = common ? true : ((offset + cnt) < sel_ties);
                cnt++;
            }
            float f = fkey_inv(k);
            h[e] = __float2half(sel ? expf(f) * sp[e] : 0.0f);
        }
        dst[tid * 4 + j] = *reinterpret_cast<const uint64_t*>(h);
    }
}

// ===========================================================================
// Kernel C: mma.sync GEMM with mbarrier-based async pipeline (no syncthreads
// in the mainloop). out[B,OUT] = g_X @ g_W^T (both K-major fp16).
// Block tile 128x256, BK=64, 4-stage cp.async; 256 threads = 8 warps (2x4),
// warp tile 64x64, fragments double-buffered across k-steps.
// full[s]: count 256, cp.async.mbarrier.arrive.noinc from every thread.
// empty[s]: count 8, one arrive per warp after its last ldsm of the stage.
// Smem rows 144 B (128 data + 16 pad) => conflict-free ldmatrix.
// ===========================================================================
#define BM 128
#define BN 256
#define BK 64
#define NSTAGE 4
#define ROWB 144
#define A_STAGE (BM * ROWB)                 // 18432
#define B_STAGE (BN * ROWB)                 // 36864
#define STAGE_BYTES (A_STAGE + B_STAGE)     // 55296
#define SMEM_TOTAL (1024 + NSTAGE * STAGE_BYTES)   // 222208
#define NITER (INN / BK)                    // 64

__device__ __forceinline__ void load_stage(int s, int tid, int m0, int n0, uint32_t tile0) {
    uint32_t aS = tile0 + (uint32_t)(s & (NSTAGE - 1)) * STAGE_BYTES;
    uint32_t bS = aS + A_STAGE;
    const __half* aG = g_X + (size_t)m0 * INN + s * BK;
    const __half* bG = g_W + (size_t)n0 * INN + s * BK;
#pragma unroll
    for (int i = 0; i < 4; i++) {            // A: 128 rows x 8 chunks of 16 B
        int t = tid + i * 256;
        int r = t >> 3, c = t & 7;
        cp16(aS + r * ROWB + c * 16, aG + (size_t)r * INN + c * 8);
    }
#pragma unroll
    for (int i = 0; i < 8; i++) {            // B: 256 rows x 8 chunks of 16 B
        int t = tid + i * 256;
        int r = t >> 3, c = t & 7;
        cp16(bS + r * ROWB + c * 16, bG + (size_t)r * INN + c * 8);
    }
}

__device__ __forceinline__ void load_frags(uint32_t aS, uint32_t bS, uint32_t kb,
                                           uint32_t a_row, uint32_t a_kof,
                                           uint32_t b_row, uint32_t b_kof,
                                           uint32_t afr[4][4], uint32_t bfr[8][2]) {
#pragma unroll
    for (int mt = 0; mt < 4; mt++)
        ldmat_x4(afr[mt][0], afr[mt][1], afr[mt][2], afr[mt][3],
                 aS + (a_row + mt * 16) * ROWB + kb + a_kof);
#pragma unroll
    for (int p = 0; p < 4; p++) {
        uint32_t r0, r1, r2, r3;
        ldmat_x4(r0, r1, r2, r3, bS + (b_row + p * 16) * ROWB + kb + b_kof);
        bfr[2 * p][0] = r0;     bfr[2 * p][1] = r1;
        bfr[2 * p + 1][0] = r2; bfr[2 * p + 1][1] = r3;
    }
}

__global__ void __launch_bounds__(256, 1) gemm_kernel(float* __restrict__ out) {
    extern __shared__ char smem[];
    const uint32_t sbase = smem_u32(smem);
    const int tid  = threadIdx.x;
    const int lane = tid & 31;
    const int wid  = tid >> 5;
    const int m0 = blockIdx.x * BM;
    const int n0 = blockIdx.y * BN;
    const int wm = (wid & 1) * 64;
    const int wn = (wid >> 1) * 64;

    const uint32_t TILE0 = sbase + 1024;
#define FULLB(i)  (sbase + (uint32_t)(i) * 8)
#define EMPTYB(i) (sbase + 32 + (uint32_t)(i) * 8)

    if (tid == 0) {
#pragma unroll
        for (int i = 0; i < NSTAGE; i++) {
            MBARRIER_INIT(FULLB(i), 256);
            MBARRIER_INIT(EMPTYB(i), 8);
        }
    }
    __syncthreads();

    float acc[4][8][4];
#pragma unroll
    for (int mt = 0; mt < 4; mt++)
#pragma unroll
        for (int nt = 0; nt < 8; nt++)
#pragma unroll
            for (int i = 0; i < 4; i++) acc[mt][nt][i] = 0.0f;

    // Prologue: stages 0..NSTAGE-2 in flight.
#pragma unroll
    for (int s = 0; s < NSTAGE - 1; s++) {
        load_stage(s, tid, m0, n0, TILE0);
        CP_MBAR_ARRIVE(FULLB(s));
    }

    const uint32_t a_row = wm + (lane & 15);
    const uint32_t a_kof = (uint32_t)(lane >> 4) * 16;
    const uint32_t b_row = wn + (lane & 7) + ((lane >> 4) << 3);
    const uint32_t b_kof = (uint32_t)((lane >> 3) & 1) * 16;

    uint32_t afr[2][4][4], bfr[2][8][2];

#pragma unroll 1
    for (int it = 0; it < NITER; it++) {
        // Produce stage it + NSTAGE - 1.
        int ps = it + NSTAGE - 1;
        if (ps < NITER) {
            if (ps >= NSTAGE) {
                // Wait until all warps consumed stage ps - NSTAGE (slot reuse).
                MBARRIER_WAIT_PARITY(EMPTYB(ps & (NSTAGE - 1)),
                                     (uint32_t)(((ps >> 2) - 1) & 1));
            }
            load_stage(ps, tid, m0, n0, TILE0);
            CP_MBAR_ARRIVE(FULLB(ps & (NSTAGE - 1)));
        }

        // Consume stage it.
        MBARRIER_WAIT_PARITY(FULLB(it & (NSTAGE - 1)), (uint32_t)((it >> 2) & 1));

        uint32_t aS = TILE0 + (uint32_t)(it & (NSTAGE - 1)) * STAGE_BYTES;
        uint32_t bS = aS + A_STAGE;

        load_frags(aS, bS, 0, a_row, a_kof, b_row, b_kof, afr[0], bfr[0]);
#pragma unroll
        for (int ks = 0; ks < 4; ks++) {
            if (ks < 3)
                load_frags(aS, bS, (uint32_t)(ks + 1) * 32, a_row, a_kof, b_row, b_kof,
                           afr[(ks + 1) & 1], bfr[(ks + 1) & 1]);
            if (ks == 2 && lane == 0) {
                // All of this warp's smem reads for stage `it` are issued
                // (ldmatrix is warp-synchronous) — release the slot.
                MBARRIER_ARRIVE(EMPTYB(it & (NSTAGE - 1)));
            }
            uint32_t (*af)[4] = afr[ks & 1];
            uint32_t (*bf)[2] = bfr[ks & 1];
#pragma unroll
            for (int mt = 0; mt < 4; mt++)
#pragma unroll
                for (int nt = 0; nt < 8; nt++)
                    mma16816(acc[mt][nt], af[mt], bf[nt]);
        }
    }

    // Epilogue.
    const int er = lane >> 2;
    const int ec = (lane & 3) * 2;
#pragma unroll
    for (int mt = 0; mt < 4; mt++) {
        int m = m0 + wm + mt * 16 + er;
#pragma unroll
        for (int nt = 0; nt < 8; nt++) {
            int n = n0 + wn + nt * 8 + ec;
            float2* p0 = reinterpret_cast<float2*>(out + (size_t)m * OUTN + n);
            float2* p1 = reinterpret_cast<float2*>(out + (size_t)(m + 8) * OUTN + n);
            *p0 = make_float2(acc[mt][nt][0], acc[mt][nt][1]);
            *p1 = make_float2(acc[mt][nt][2], acc[mt][nt][3]);
        }
    }
}

// ===========================================================================
extern "C" void kernel_launch(void* const* d_in, const int* in_sizes, int n_in,
                              void* d_out, int out_size) {
    const float* x      = (const float*)d_in[0];
    const float* pre_w  = (const float*)d_in[1];
    const float* sign_m = (const float*)d_in[2];
    float* out = (float*)d_out;

    cudaFuncSetAttribute(gemm_kernel, cudaFuncAttributeMaxDynamicSharedMemorySize, SMEM_TOTAL);

    prep_kernel<<<OUTN + CONV_BLKS, 256>>>(pre_w, sign_m, x);
    gemm_kernel<<<dim3(BATCH / BM, OUTN / BN), 256, SMEM_TOTAL>>>(out);
}